// round 3
// baseline (speedup 1.0000x reference)
#include <cuda_runtime.h>
#include <cuda_bf16.h>

// RoiAlign: fm (1,256,50,50) f32, proposals (1024,4) f32 -> out (1024,256,7,7) f32
// Reference double-applies SCALE (1/16 twice => /256); roi_w/h clamp to >=1, so each
// box's sampled patch spans <=4 rows/cols -> separable fast path:
//   out[oy][ox] = sum_{y,x} Wy[oy][y] * Wx[ox][x] * patch[y][x],
//   Wy[oy][r] = 0.5 * sum over the bin's 2 subsamples of bilinear weight at row r.
//
// Block = 128 threads = 128 channels (half a box); grid = (1024, 2).
// Results staged in 25KB smem (each thread stages its own channel -> no idle
// threads, 2 barriers total), then block-wide coalesced float4 copy to gmem.

#define C_CH  256
#define HH    50
#define WW    50
#define OUTSZ 7
#define SSAMP 14   // OUT * SR
#define SPAN  4    // max patch extent per axis for fast path
#define BTH   128  // threads / channels per block

__global__ __launch_bounds__(BTH)
void roi_align_kernel(const float* __restrict__ fm,
                      const float* __restrict__ proposals,
                      float* __restrict__ out)
{
    const int n    = blockIdx.x;
    const int half = blockIdx.y;
    const int tid  = threadIdx.x;
    const int c    = half * BTH + tid;

    // Unified axis arrays: Y samples at [0..13], X samples at [14..27]
    __shared__ float s_h[2 * SSAMP], s_l[2 * SSAMP];
    __shared__ int   s_a0[2 * SSAMP], s_a1[2 * SSAMP];
    __shared__ float sWy[OUTSZ][SPAN], sWx[OUTSZ][SPAN];
    __shared__ int   s_base[2];     // [0]=ybase, [1]=xbase
    __shared__ int   s_okArr[2];
    __shared__ int   s_yoff[SPAN];  // clamped row offsets (*WW)
    __shared__ int   s_xoff[SPAN];  // clamped col offsets
    __shared__ __align__(16) float s_stage[BTH * 49];   // 25088 B

    // ---------- setup: warp 0, warp-level syncs ----------
    if (tid < 32) {
        if (tid < 2 * SSAMP) {
            const bool isY = tid < SSAMP;
            const int  s   = isY ? tid : tid - SSAMP;
            float4 p = reinterpret_cast<const float4*>(proposals)[n];
            const float sc = 0.0625f;
            float x1 = (p.x * sc) * sc, y1v = (p.y * sc) * sc;
            float x2 = (p.z * sc) * sc, y2v = (p.w * sc) * sc;
            float roiw = fmaxf(x2 - x1, 1.0f);
            float roih = fmaxf(y2v - y1v, 1.0f);
            float g = ((float)s + 0.5f) * 0.5f;              // (s+0.5)/SR
            float v = isY ? (y1v + (roih * (1.0f / 7.0f)) * g)
                          : (x1  + (roiw * (1.0f / 7.0f)) * g);
            const int L = isY ? HH : WW;                      // both 50
            bool valid = (v >= -1.0f) && (v <= (float)L);
            float vc = fminf(fmaxf(v, 0.0f), (float)(L - 1));
            int i0 = min((int)floorf(vc), L - 1);
            int i1 = min(i0 + 1, L - 1);
            float l = vc - (float)i0;
            float h = 1.0f - l;
            if (!valid) { h = 0.0f; l = 0.0f; }
            s_a0[tid] = i0; s_a1[tid] = i1; s_h[tid] = h; s_l[tid] = l;
        }
        __syncwarp();
        if (tid < 2) {   // per-axis patch bounds
            const int off = tid * SSAMP;
            int mn = 1 << 30, mx = -1;
            #pragma unroll
            for (int s = 0; s < SSAMP; s++) {
                mn = min(mn, s_a0[off + s]);
                mx = max(mx, s_a1[off + s]);
            }
            s_base[tid]  = mn;
            s_okArr[tid] = ((mx - mn) < SPAN) ? 1 : 0;
        }
        __syncwarp();
        if (tid < 2 * OUTSZ) {      // combined separable bin weights
            const bool isY = tid < OUTSZ;
            const int  o   = isY ? tid : tid - OUTSZ;
            const int  off = isY ? 0 : SSAMP;
            const int  base = s_base[isY ? 0 : 1];
            float w[SPAN] = {0.f, 0.f, 0.f, 0.f};
            #pragma unroll
            for (int k = 0; k < 2; k++) {
                int s = off + 2 * o + k;
                w[min(s_a0[s] - base, SPAN - 1)] += 0.5f * s_h[s];
                w[min(s_a1[s] - base, SPAN - 1)] += 0.5f * s_l[s];
            }
            #pragma unroll
            for (int j = 0; j < SPAN; j++) {
                if (isY) sWy[o][j] = w[j]; else sWx[o][j] = w[j];
            }
        } else if (tid < 2 * OUTSZ + SPAN) {
            int i = tid - 2 * OUTSZ;
            s_yoff[i] = min(s_base[0] + i, HH - 1) * WW;
        } else if (tid < 2 * OUTSZ + 2 * SPAN) {
            int i = tid - 2 * OUTSZ - SPAN;
            s_xoff[i] = min(s_base[1] + i, WW - 1);
        }
    }
    __syncthreads();

    const bool ok = (s_okArr[0] != 0) && (s_okArr[1] != 0);
    const float* fmc = fm + (size_t)c * (HH * WW);

    if (ok) {
        // ---------- separable fast path: thread = channel ----------
        const int xo0 = s_xoff[0], xo1 = s_xoff[1], xo2 = s_xoff[2], xo3 = s_xoff[3];

        float r0[SPAN], r1[SPAN], r2[SPAN], r3[SPAN];
        #pragma unroll
        for (int y = 0; y < SPAN; y++) {
            const float* rp = fmc + s_yoff[y];
            r0[y] = rp[xo0]; r1[y] = rp[xo1]; r2[y] = rp[xo2]; r3[y] = rp[xo3];
        }

        float sx[SPAN][OUTSZ];
        #pragma unroll
        for (int o = 0; o < OUTSZ; o++) {
            float w0 = sWx[o][0], w1 = sWx[o][1], w2 = sWx[o][2], w3 = sWx[o][3];
            #pragma unroll
            for (int y = 0; y < SPAN; y++)
                sx[y][o] = r0[y] * w0 + r1[y] * w1 + r2[y] * w2 + r3[y] * w3;
        }

        // final combine written directly to stage smem
        float* st = s_stage + tid * 49;
        #pragma unroll
        for (int oy = 0; oy < OUTSZ; oy++) {
            float wy0 = sWy[oy][0], wy1 = sWy[oy][1], wy2 = sWy[oy][2], wy3 = sWy[oy][3];
            #pragma unroll
            for (int ox = 0; ox < OUTSZ; ox++)
                st[oy * 7 + ox] = wy0 * sx[0][ox] + wy1 * sx[1][ox]
                                + wy2 * sx[2][ox] + wy3 * sx[3][ox];
        }
    } else {
        // ---------- general fallback (block-uniform, direct stores) ----------
        float* outc = out + ((size_t)n * C_CH + c) * 49;
        for (int oy = 0; oy < OUTSZ; oy++) {
            for (int ox = 0; ox < OUTSZ; ox++) {
                float a = 0.0f;
                #pragma unroll
                for (int ky = 0; ky < 2; ky++) {
                    int sy = 2 * oy + ky;
                    int y0 = s_a0[sy] * WW, y1i = s_a1[sy] * WW;
                    float hy = s_h[sy], ly = s_l[sy];
                    #pragma unroll
                    for (int kx = 0; kx < 2; kx++) {
                        int sxi = SSAMP + 2 * ox + kx;
                        int x0 = s_a0[sxi], x1i = s_a1[sxi];
                        float hx = s_h[sxi], lx = s_l[sxi];
                        a += hy * (hx * fmc[y0 + x0]  + lx * fmc[y0 + x1i])
                           + ly * (hx * fmc[y1i + x0] + lx * fmc[y1i + x1i]);
                    }
                }
                outc[oy * 7 + ox] = a * 0.25f;
            }
        }
    }

    __syncthreads();

    if (ok) {
        // ---------- coalesced block store: 1568 float4 by 128 threads ----------
        float4* dst = reinterpret_cast<float4*>(
            out + (size_t)n * (C_CH * 49) + (size_t)half * (BTH * 49));
        const float4* src = reinterpret_cast<const float4*>(s_stage);
        #pragma unroll 1
        for (int i = tid; i < (BTH * 49) / 4; i += BTH)
            dst[i] = src[i];
    }
}

extern "C" void kernel_launch(void* const* d_in, const int* in_sizes, int n_in,
                              void* d_out, int out_size) {
    const float* fm    = (const float*)d_in[0];   // (1,256,50,50) f32
    const float* props = (const float*)d_in[1];   // (1024,4) f32
    float* out         = (float*)d_out;           // (1024,256,7,7) f32
    int N = in_sizes[1] / 4;
    dim3 grid(N, 2);
    roi_align_kernel<<<grid, BTH>>>(fm, props, out);
}

// round 6
// speedup vs baseline: 1.3594x; 1.3594x over previous
#include <cuda_runtime.h>
#include <cuda_bf16.h>

// RoiAlign: fm (1,256,50,50) f32, proposals (1024,4) f32 -> out (1024,256,7,7) f32
// Reference double-applies SCALE => /256, roi_w/h clamped >=1. Under the bench's
// box distribution every sample coord is in [0, 3.23], so ALL boxes read only
// fm[:, 0:5, 0:5]. We cache that 5x5 patch per channel in smem/registers once
// per block and reuse it across G boxes; only the tiny separable weight tables
// (Wy[7][5], Wx[7][5], base 0) differ per box. Runtime-validated with a gmem
// fallback per box if a patch ever exceeds [0,4].

#define C_CH  256
#define HH    50
#define WW    50
#define OUTSZ 7
#define SSAMP 14    // OUT * SR
#define SPAN  5     // fixed patch 0..4 per axis
#define BTH   128   // threads = channels per block-half
#define GBOX  2     // boxes per block

__global__ __launch_bounds__(BTH)
void roi_align_kernel(const float* __restrict__ fm,
                      const float* __restrict__ proposals,
                      float* __restrict__ out)
{
    const int tid  = threadIdx.x;
    const int half = blockIdx.y;
    const int n0   = blockIdx.x * GBOX;

    __shared__ float s_fm[BTH * 25];                    // 12.8 KB hot patch
    __shared__ __align__(16) float s_stage[BTH * 49];   // 25 KB store stage
    __shared__ float s_h[GBOX * 2 * SSAMP], s_l[GBOX * 2 * SSAMP];
    __shared__ int   s_a0[GBOX * 2 * SSAMP], s_a1[GBOX * 2 * SSAMP];
    __shared__ float sWy[GBOX][OUTSZ][SPAN], sWx[GBOX][OUTSZ][SPAN];
    __shared__ int   s_ok[GBOX];

    // ---------- cooperative fill of hot fm patch (once per block) ----------
    {
        const float* fmh = fm + (size_t)(half * BTH) * (HH * WW);
        #pragma unroll 1
        for (int i = tid; i < BTH * 25; i += BTH) {
            int ch = i / 25, k = i % 25;
            s_fm[i] = fmh[ch * (HH * WW) + (k / 5) * WW + (k % 5)];
        }
    }

    // ---------- per-box axis sample params: GBOX*28 = 56 threads ----------
    if (tid < GBOX * 2 * SSAMP) {
        const int g = tid / (2 * SSAMP);
        const int j = tid % (2 * SSAMP);
        const bool isY = j < SSAMP;
        const int  s   = isY ? j : j - SSAMP;
        float4 p = reinterpret_cast<const float4*>(proposals)[n0 + g];
        const float sc = 0.0625f;
        float x1 = (p.x * sc) * sc, y1v = (p.y * sc) * sc;
        float x2 = (p.z * sc) * sc, y2v = (p.w * sc) * sc;
        float roiw = fmaxf(x2 - x1, 1.0f);
        float roih = fmaxf(y2v - y1v, 1.0f);
        float gg = ((float)s + 0.5f) * 0.5f;              // (s+0.5)/SR
        float v = isY ? (y1v + (roih * (1.0f / 7.0f)) * gg)
                      : (x1  + (roiw * (1.0f / 7.0f)) * gg);
        const int L = HH;                                  // H == W == 50
        bool valid = (v >= -1.0f) && (v <= (float)L);
        float vc = fminf(fmaxf(v, 0.0f), (float)(L - 1));
        int i0 = min((int)floorf(vc), L - 1);
        int i1 = min(i0 + 1, L - 1);
        float l = vc - (float)i0;
        float h = 1.0f - l;
        if (!valid) { h = 0.0f; l = 0.0f; }
        s_a0[tid] = i0; s_a1[tid] = i1; s_h[tid] = h; s_l[tid] = l;
    }
    __syncthreads();

    // ---------- weights (GBOX*14 threads) + validity flags ----------
    if (tid < GBOX * 2 * OUTSZ) {
        const int g = tid / (2 * OUTSZ);
        const int j = tid % (2 * OUTSZ);
        const bool isY = j < OUTSZ;
        const int  o   = isY ? j : j - OUTSZ;
        const int  off = g * 2 * SSAMP + (isY ? 0 : SSAMP);
        float w[SPAN] = {0.f, 0.f, 0.f, 0.f, 0.f};
        #pragma unroll
        for (int k = 0; k < 2; k++) {
            int s = off + 2 * o + k;
            w[min(s_a0[s], SPAN - 1)] += 0.5f * s_h[s];
            w[min(s_a1[s], SPAN - 1)] += 0.5f * s_l[s];
        }
        #pragma unroll
        for (int q = 0; q < SPAN; q++) {
            if (isY) sWy[g][o][q] = w[q]; else sWx[g][o][q] = w[q];
        }
    } else if (tid >= 64 && tid < 64 + GBOX) {
        const int g = tid - 64;
        int mx = -1;
        #pragma unroll
        for (int s = 0; s < 2 * SSAMP; s++)
            mx = max(mx, s_a1[g * 2 * SSAMP + s]);
        s_ok[g] = (mx <= SPAN - 1) ? 1 : 0;
    }
    __syncthreads();

    // ---------- preload this channel's 25 patch values (conflict-free LDS) ----------
    float r[25];
    #pragma unroll
    for (int k = 0; k < 25; k++) r[k] = s_fm[tid * 25 + k];

    const int c = half * BTH + tid;
    const float* fmc = fm + (size_t)c * (HH * WW);

    #pragma unroll 1
    for (int g = 0; g < GBOX; g++) {
        float* outb = out + (size_t)(n0 + g) * (C_CH * 49);
        if (s_ok[g]) {
            // separable: sx[y][o] = sum_x r[y][x] * Wx[o][x]
            float sx[SPAN][OUTSZ];
            #pragma unroll
            for (int o = 0; o < OUTSZ; o++) {
                float w0 = sWx[g][o][0], w1 = sWx[g][o][1], w2 = sWx[g][o][2];
                float w3 = sWx[g][o][3], w4 = sWx[g][o][4];
                #pragma unroll
                for (int y = 0; y < SPAN; y++)
                    sx[y][o] = r[y*5+0]*w0 + r[y*5+1]*w1 + r[y*5+2]*w2
                             + r[y*5+3]*w3 + r[y*5+4]*w4;
            }
            float* st = s_stage + tid * 49;
            #pragma unroll
            for (int oy = 0; oy < OUTSZ; oy++) {
                float wy0 = sWy[g][oy][0], wy1 = sWy[g][oy][1], wy2 = sWy[g][oy][2];
                float wy3 = sWy[g][oy][3], wy4 = sWy[g][oy][4];
                #pragma unroll
                for (int ox = 0; ox < OUTSZ; ox++)
                    st[oy * 7 + ox] = wy0*sx[0][ox] + wy1*sx[1][ox] + wy2*sx[2][ox]
                                    + wy3*sx[3][ox] + wy4*sx[4][ox];
            }
        } else {
            // ---------- general fallback: direct gmem compute + store ----------
            float* outc = outb + (size_t)c * 49;
            const int off = g * 2 * SSAMP;
            for (int oy = 0; oy < OUTSZ; oy++) {
                for (int ox = 0; ox < OUTSZ; ox++) {
                    float a = 0.0f;
                    #pragma unroll
                    for (int ky = 0; ky < 2; ky++) {
                        int sy = off + 2 * oy + ky;
                        int y0 = s_a0[sy] * WW, y1i = s_a1[sy] * WW;
                        float hy = s_h[sy], ly = s_l[sy];
                        #pragma unroll
                        for (int kx = 0; kx < 2; kx++) {
                            int sxi = off + SSAMP + 2 * ox + kx;
                            int x0 = s_a0[sxi], x1i = s_a1[sxi];
                            float hx = s_h[sxi], lx = s_l[sxi];
                            a += hy * (hx * fmc[y0 + x0]  + lx * fmc[y0 + x1i])
                               + ly * (hx * fmc[y1i + x0] + lx * fmc[y1i + x1i]);
                        }
                    }
                    outc[oy * 7 + ox] = a * 0.25f;
                }
            }
        }
        __syncthreads();

        if (s_ok[g]) {
            // coalesced block store: 1568 float4 by 128 threads
            float4* dst = reinterpret_cast<float4*>(outb + (size_t)half * (BTH * 49));
            const float4* src = reinterpret_cast<const float4*>(s_stage);
            #pragma unroll 1
            for (int i = tid; i < (BTH * 49) / 4; i += BTH)
                dst[i] = src[i];
        }
        __syncthreads();
    }
}

extern "C" void kernel_launch(void* const* d_in, const int* in_sizes, int n_in,
                              void* d_out, int out_size) {
    const float* fm    = (const float*)d_in[0];   // (1,256,50,50) f32
    const float* props = (const float*)d_in[1];   // (1024,4) f32
    float* out         = (float*)d_out;           // (1024,256,7,7) f32
    int N = in_sizes[1] / 4;
    dim3 grid(N / GBOX, 2);
    roi_align_kernel<<<grid, BTH>>>(fm, props, out);
}